// round 8
// baseline (speedup 1.0000x reference)
#include <cuda_runtime.h>
#include <math.h>

#define B_      8
#define C_      512
#define K_      19
#define HW_     16384
#define NCHUNK  64            // px chunks per image for pooling partials
#define PXT     256           // pixels per k1b block
#define XSPAD   516           // padded u64 row width for x px-pair slab

typedef unsigned long long u64;

__device__ __forceinline__ u64 ffma2(u64 a, u64 b, u64 c) {
    u64 d; asm("fma.rn.f32x2 %0, %1, %2, %3;" : "=l"(d) : "l"(a), "l"(b), "l"(c)); return d;
}
__device__ __forceinline__ u64 pack2(float lo, float hi) {
    u64 d; asm("mov.b64 %0, {%1, %2};" : "=l"(d) : "f"(lo), "f"(hi)); return d;
}
__device__ __forceinline__ float2 unpack2(u64 v) {
    float2 r; asm("mov.b64 {%0, %1}, %2;" : "=f"(r.x), "=f"(r.y) : "l"(v)); return r;
}

// Scratch (device globals — no allocation allowed)
__device__ float g_mask[B_ * K_ * HW_];               // ~10 MB
__device__ float g_partial[B_ * NCHUNK * K_ * C_];    // ~19.9 MB
__device__ float g_cf[B_ * K_ * C_];
__device__ float g_filters[B_ * K_ * C_];

// -------------------------------------------------------------------------
// k1a: mask[b,k,p] = sigmoid(sum_c Wm[k,c] x[b,c,p] + bm[k])
// 256 blocks (b x 32 segs), 256 thr, 2 px/thread, FFMA2 over c-pairs.
// Prefetch distance 2: 8 float2 x-loads in flight per thread.
// -------------------------------------------------------------------------
__global__ __launch_bounds__(256)
void k1a_mask(const float* __restrict__ x,
              const float* __restrict__ Wm,
              const float* __restrict__ bm)
{
    __shared__ __align__(16) float Wm_s[K_ * C_];   // 38912 B
    __shared__ float bm_s[K_];

    const int t   = threadIdx.x;
    const int b   = blockIdx.x >> 5;
    const int seg = blockIdx.x & 31;
    const int p0  = seg * 512 + t * 2;

    for (int i = t; i < K_ * C_; i += 256) Wm_s[i] = Wm[i];
    if (t < K_) bm_s[t] = bm[t];

    const float* xp = x + (size_t)b * C_ * HW_ + p0;

    u64 acc[K_][2];
    #pragma unroll
    for (int k = 0; k < K_; k++) { acc[k][0] = 0ull; acc[k][1] = 0ull; }

    __syncthreads();

    float2 A[4], Bv[4];
    #pragma unroll
    for (int j = 0; j < 4; j++) A[j]  = *(const float2*)(xp + (size_t)j * HW_);
    #pragma unroll
    for (int j = 0; j < 4; j++) Bv[j] = *(const float2*)(xp + (size_t)(4 + j) * HW_);

    for (int c = 0; c < C_; c += 8) {
        // ---- half 1: rows c..c+3 (in A) ----
        {
            const u64 a0 = pack2(A[0].x, A[1].x);
            const u64 b0 = pack2(A[2].x, A[3].x);
            const u64 a1 = pack2(A[0].y, A[1].y);
            const u64 b1 = pack2(A[2].y, A[3].y);
            if (c + 8 < C_) {
                #pragma unroll
                for (int j = 0; j < 4; j++)
                    A[j] = *(const float2*)(xp + (size_t)(c + 8 + j) * HW_);
            }
            #pragma unroll
            for (int k = 0; k < K_; k++) {
                const ulonglong2 w = *(const ulonglong2*)&Wm_s[k * C_ + c];
                acc[k][0] = ffma2(a0, w.x, acc[k][0]);
                acc[k][0] = ffma2(b0, w.y, acc[k][0]);
                acc[k][1] = ffma2(a1, w.x, acc[k][1]);
                acc[k][1] = ffma2(b1, w.y, acc[k][1]);
            }
        }
        // ---- half 2: rows c+4..c+7 (in Bv) ----
        {
            const u64 a0 = pack2(Bv[0].x, Bv[1].x);
            const u64 b0 = pack2(Bv[2].x, Bv[3].x);
            const u64 a1 = pack2(Bv[0].y, Bv[1].y);
            const u64 b1 = pack2(Bv[2].y, Bv[3].y);
            if (c + 12 < C_) {
                #pragma unroll
                for (int j = 0; j < 4; j++)
                    Bv[j] = *(const float2*)(xp + (size_t)(c + 12 + j) * HW_);
            }
            #pragma unroll
            for (int k = 0; k < K_; k++) {
                const ulonglong2 w = *(const ulonglong2*)&Wm_s[k * C_ + c + 4];
                acc[k][0] = ffma2(a0, w.x, acc[k][0]);
                acc[k][0] = ffma2(b0, w.y, acc[k][0]);
                acc[k][1] = ffma2(a1, w.x, acc[k][1]);
                acc[k][1] = ffma2(b1, w.y, acc[k][1]);
            }
        }
    }

    float* mb = g_mask + (size_t)b * K_ * HW_ + p0;
    #pragma unroll
    for (int k = 0; k < K_; k++) {
        const float2 f0 = unpack2(acc[k][0]);
        const float2 f1 = unpack2(acc[k][1]);
        const float s0 = f0.x + f0.y + bm_s[k];
        const float s1 = f1.x + f1.y + bm_s[k];
        float2 m;
        m.x = 1.0f / (1.0f + __expf(-s0));
        m.y = 1.0f / (1.0f + __expf(-s1));
        *(float2*)(mb + (size_t)k * HW_) = m;
    }
}

// -------------------------------------------------------------------------
// k1b: partial[b,ch,k,c] = sum_{p in 256-px chunk} mask[b,k,p] * x[b,c,p]
// 512 blocks (b x 64 chunks), 512 thr (thread = single c).
// FFMA2 lanes = px-pairs; mask staged as u64 px-pairs (LDS.128 broadcast).
// x staged per 8-px slab into DOUBLE-BUFFERED smem: next slab's LDGs issue
// before computing the current slab -> one barrier/slab, latency hidden.
// Dynamic smem: mask2 (19456 B) + 2 x-slabs (33024 B) = 52480 B.
// -------------------------------------------------------------------------
#define K1B_SMEM (K_ * 128 * 8 + 2 * 4 * XSPAD * 8)

__global__ __launch_bounds__(512, 2)
void k1b_pool(const float* __restrict__ x)
{
    extern __shared__ __align__(16) unsigned char smraw[];
    u64 (*mask2_s)[128]  = (u64(*)[128])smraw;                       // [K_][128]
    u64 (*x2_s)[4][XSPAD] = (u64(*)[4][XSPAD])(smraw + K_ * 128 * 8); // [2][4][XSPAD]

    const int t     = threadIdx.x;
    const int b     = blockIdx.x >> 6;
    const int ch    = blockIdx.x & 63;
    const int pbase = ch * PXT;
    const int c     = t;

    // stage mask px-pairs (coalesced 8B loads)
    {
        const u64* mb = (const u64*)(g_mask + (size_t)b * K_ * HW_ + pbase);
        for (int i = t; i < K_ * 128; i += 512) {
            const int k  = i >> 7;
            const int pr = i & 127;
            mask2_s[k][pr] = mb[(size_t)k * (HW_ / 2) + pr];
        }
    }

    const float* xb = x + (size_t)b * C_ * HW_ + pbase;

    u64 acc[K_];
    #pragma unroll
    for (int k = 0; k < K_; k++) acc[k] = 0ull;

    // stage-loop thread mapping: idx = it*512+t -> (cc = idx>>1, q = idx&1)
    const int cc = t >> 1;          // it contributes +256 to cc
    const int q  = t & 1;

    // preload slab 0 into regs, store to buf 0
    float4 v0 = *(const float4*)&xb[(size_t)cc * HW_ + q * 4];
    float4 v1 = *(const float4*)&xb[(size_t)(cc + 256) * HW_ + q * 4];
    x2_s[0][q * 2 + 0][cc]       = pack2(v0.x, v0.y);
    x2_s[0][q * 2 + 1][cc]       = pack2(v0.z, v0.w);
    x2_s[0][q * 2 + 0][cc + 256] = pack2(v1.x, v1.y);
    x2_s[0][q * 2 + 1][cc + 256] = pack2(v1.z, v1.w);
    __syncthreads();

    for (int s = 0; s < PXT / 8; s++) {
        const int cur = s & 1;
        // prefetch slab s+1 (LDGs in flight during compute)
        if (s + 1 < PXT / 8) {
            const int pp = (s + 1) * 8;
            v0 = *(const float4*)&xb[(size_t)cc * HW_ + pp + q * 4];
            v1 = *(const float4*)&xb[(size_t)(cc + 256) * HW_ + pp + q * 4];
        }

        // compute slab s: 4 px-pairs
        const int colb = s * 4;
        #pragma unroll
        for (int pw = 0; pw < 4; pw += 2) {
            const u64 xv0 = x2_s[cur][pw + 0][c];
            const u64 xv1 = x2_s[cur][pw + 1][c];
            #pragma unroll
            for (int k = 0; k < K_; k++) {
                const ulonglong2 m = *(const ulonglong2*)&mask2_s[k][colb + pw];  // broadcast
                acc[k] = ffma2(xv0, m.x, acc[k]);
                acc[k] = ffma2(xv1, m.y, acc[k]);
            }
        }

        // store prefetched slab into the other buffer
        if (s + 1 < PXT / 8) {
            const int nxt = cur ^ 1;
            x2_s[nxt][q * 2 + 0][cc]       = pack2(v0.x, v0.y);
            x2_s[nxt][q * 2 + 1][cc]       = pack2(v0.z, v0.w);
            x2_s[nxt][q * 2 + 0][cc + 256] = pack2(v1.x, v1.y);
            x2_s[nxt][q * 2 + 1][cc + 256] = pack2(v1.z, v1.w);
        }
        __syncthreads();
    }

    float* dst = g_partial + (size_t)(b * NCHUNK + ch) * K_ * C_;
    #pragma unroll
    for (int k = 0; k < K_; k++) {
        const float2 f = unpack2(acc[k]);
        dst[k * C_ + c] = f.x + f.y;
    }
}

// -------------------------------------------------------------------------
// k2: deterministic reduction of partials -> class_feat / (h*w)
// -------------------------------------------------------------------------
__global__ __launch_bounds__(512)
void k2_reduce()
{
    const int bk = blockIdx.x;
    const int c  = threadIdx.x;
    const int b  = bk / K_;
    const int k  = bk % K_;

    const float* src = g_partial + ((size_t)b * NCHUNK * K_ + k) * C_ + c;
    float s = 0.f;
    #pragma unroll 8
    for (int ch = 0; ch < NCHUNK; ch++)
        s += src[(size_t)ch * K_ * C_];
    g_cf[(b * K_ + k) * C_ + c] = s * (1.0f / (float)HW_);
}

// -------------------------------------------------------------------------
// k3: filters[b,k,o] = sum_c Wf[k,o,c] * cf[b,k,c] + bf[k,o]
// Grid (19, 64), 256 thr; warp owns one o, lane owns c-chunk (coalesced Wf).
// -------------------------------------------------------------------------
__global__ __launch_bounds__(256)
void k3_filters(const float* __restrict__ Wf, const float* __restrict__ bf)
{
    __shared__ __align__(16) float cf_s[B_][XSPAD];   // 16512 B

    const int k    = blockIdx.x;
    const int og   = blockIdx.y;
    const int t    = threadIdx.x;
    const int w    = t >> 5;
    const int lane = t & 31;
    const int o    = og * 8 + w;

    for (int i = t; i < B_ * C_; i += 256) {
        const int bb = i >> 9;
        const int cc = i & 511;
        cf_s[bb][cc] = g_cf[(bb * K_ + k) * C_ + cc];
    }
    __syncthreads();

    const float* wrow = Wf + ((size_t)k * C_ + o) * C_;

    float acc[B_];
    #pragma unroll
    for (int bb = 0; bb < B_; bb++) acc[bb] = 0.f;

    #pragma unroll
    for (int ccq = 0; ccq < 4; ccq++) {
        const int cbase = ccq * 128 + lane * 4;
        const float4 wv = *(const float4*)(wrow + cbase);
        #pragma unroll
        for (int bb = 0; bb < B_; bb++) {
            const float4 f = *(const float4*)&cf_s[bb][cbase];
            acc[bb] = fmaf(wv.x, f.x,
                      fmaf(wv.y, f.y,
                      fmaf(wv.z, f.z,
                      fmaf(wv.w, f.w, acc[bb]))));
        }
    }

    #pragma unroll
    for (int off = 16; off >= 1; off >>= 1) {
        #pragma unroll
        for (int bb = 0; bb < B_; bb++)
            acc[bb] += __shfl_xor_sync(0xffffffffu, acc[bb], off);
    }

    if (lane < B_)
        g_filters[((size_t)lane * K_ + k) * C_ + o] = acc[lane] + bf[k * C_ + o];
}

// -------------------------------------------------------------------------
// k4: pred[b,k,p] = sum_c filters[b,k,c] * x[b,c,p]
// Same structure as k1a (2 px/thread, prefetch distance 2).
// -------------------------------------------------------------------------
__global__ __launch_bounds__(256)
void k4_pred(const float* __restrict__ x, float* __restrict__ out)
{
    __shared__ __align__(16) float f_s[K_ * C_];   // 38912 B

    const int t   = threadIdx.x;
    const int b   = blockIdx.x >> 5;
    const int seg = blockIdx.x & 31;
    const int p0  = seg * 512 + t * 2;

    for (int i = t; i < K_ * C_; i += 256)
        f_s[i] = g_filters[(size_t)b * K_ * C_ + i];

    const float* xp = x + (size_t)b * C_ * HW_ + p0;

    u64 acc[K_][2];
    #pragma unroll
    for (int k = 0; k < K_; k++) { acc[k][0] = 0ull; acc[k][1] = 0ull; }

    __syncthreads();

    float2 A[4], Bv[4];
    #pragma unroll
    for (int j = 0; j < 4; j++) A[j]  = *(const float2*)(xp + (size_t)j * HW_);
    #pragma unroll
    for (int j = 0; j < 4; j++) Bv[j] = *(const float2*)(xp + (size_t)(4 + j) * HW_);

    for (int c = 0; c < C_; c += 8) {
        {
            const u64 a0 = pack2(A[0].x, A[1].x);
            const u64 b0 = pack2(A[2].x, A[3].x);
            const u64 a1 = pack2(A[0].y, A[1].y);
            const u64 b1 = pack2(A[2].y, A[3].y);
            if (c + 8 < C_) {
                #pragma unroll
                for (int j = 0; j < 4; j++)
                    A[j] = *(const float2*)(xp + (size_t)(c + 8 + j) * HW_);
            }
            #pragma unroll
            for (int k = 0; k < K_; k++) {
                const ulonglong2 w = *(const ulonglong2*)&f_s[k * C_ + c];
                acc[k][0] = ffma2(a0, w.x, acc[k][0]);
                acc[k][0] = ffma2(b0, w.y, acc[k][0]);
                acc[k][1] = ffma2(a1, w.x, acc[k][1]);
                acc[k][1] = ffma2(b1, w.y, acc[k][1]);
            }
        }
        {
            const u64 a0 = pack2(Bv[0].x, Bv[1].x);
            const u64 b0 = pack2(Bv[2].x, Bv[3].x);
            const u64 a1 = pack2(Bv[0].y, Bv[1].y);
            const u64 b1 = pack2(Bv[2].y, Bv[3].y);
            if (c + 12 < C_) {
                #pragma unroll
                for (int j = 0; j < 4; j++)
                    Bv[j] = *(const float2*)(xp + (size_t)(c + 12 + j) * HW_);
            }
            #pragma unroll
            for (int k = 0; k < K_; k++) {
                const ulonglong2 w = *(const ulonglong2*)&f_s[k * C_ + c + 4];
                acc[k][0] = ffma2(a0, w.x, acc[k][0]);
                acc[k][0] = ffma2(b0, w.y, acc[k][0]);
                acc[k][1] = ffma2(a1, w.x, acc[k][1]);
                acc[k][1] = ffma2(b1, w.y, acc[k][1]);
            }
        }
    }

    float* ob = out + (size_t)b * K_ * HW_ + p0;
    #pragma unroll
    for (int k = 0; k < K_; k++) {
        const float2 f0 = unpack2(acc[k][0]);
        const float2 f1 = unpack2(acc[k][1]);
        float2 v; v.x = f0.x + f0.y; v.y = f1.x + f1.y;
        *(float2*)(ob + (size_t)k * HW_) = v;
    }
}

// -------------------------------------------------------------------------
extern "C" void kernel_launch(void* const* d_in, const int* in_sizes, int n_in,
                              void* d_out, int out_size)
{
    const float* x  = (const float*)d_in[0];
    const float* Wm = (const float*)d_in[1];
    const float* bm = (const float*)d_in[2];
    const float* Wf = (const float*)d_in[3];
    const float* bf = (const float*)d_in[4];
    float* out = (float*)d_out;

    static int smem_set = 0;
    if (!smem_set) {
        cudaFuncSetAttribute(k1b_pool, cudaFuncAttributeMaxDynamicSharedMemorySize, K1B_SMEM);
        smem_set = 1;
    }

    k1a_mask  <<<B_ * 32, 256>>>(x, Wm, bm);
    k1b_pool  <<<B_ * NCHUNK, 512, K1B_SMEM>>>(x);
    k2_reduce <<<B_ * K_, 512>>>();
    k3_filters<<<dim3(K_, 64), 256>>>(Wf, bf);
    k4_pred   <<<B_ * 32, 256>>>(x, out);
}

// round 9
// speedup vs baseline: 1.4491x; 1.4491x over previous
#include <cuda_runtime.h>
#include <math.h>

#define B_      8
#define C_      512
#define K_      19
#define HW_     16384
#define CH_     256           // c-half for k1a
#define NCHUNK  32            // px chunks per image for pooling partials
#define PXT     512           // k1b pixels per block
#define XROW    36            // k1b padded x-row width (floats)

typedef unsigned long long u64;

__device__ __forceinline__ u64 ffma2(u64 a, u64 b, u64 c) {
    u64 d; asm("fma.rn.f32x2 %0, %1, %2, %3;" : "=l"(d) : "l"(a), "l"(b), "l"(c)); return d;
}
__device__ __forceinline__ u64 pack2(float lo, float hi) {
    u64 d; asm("mov.b64 %0, {%1, %2};" : "=l"(d) : "f"(lo), "f"(hi)); return d;
}
__device__ __forceinline__ float2 unpack2(u64 v) {
    float2 r; asm("mov.b64 {%0, %1}, %2;" : "=f"(r.x), "=f"(r.y) : "l"(v)); return r;
}
__device__ __forceinline__ void cp16(void* smem_dst, const void* gmem_src) {
    unsigned sa = (unsigned)__cvta_generic_to_shared(smem_dst);
    asm volatile("cp.async.cg.shared.global [%0], [%1], 16;" :: "r"(sa), "l"(gmem_src));
}
__device__ __forceinline__ void cp_commit() {
    asm volatile("cp.async.commit_group;");
}
__device__ __forceinline__ void cp_wait_all() {
    asm volatile("cp.async.wait_group 0;");
}

// Scratch (device globals — no allocation allowed)
__device__ float g_pm[2 * B_ * K_ * HW_];             // pre-mask partials (2 c-halves), ~19.9 MB
__device__ float g_partial[B_ * NCHUNK * K_ * C_];    // pooling partials, ~10 MB
__device__ float g_cf[B_ * K_ * C_];
__device__ float g_filters[B_ * K_ * C_];

// -------------------------------------------------------------------------
// k1a: pre-mask c-half partial: pm[h,b,k,p] = sum_{c in half} Wm[k,c] x[b,c,p]
// Grid 256 = h(2) x b(8) x seg(16 of 1024px). 256 thr, 4 px/thread.
// x staged 16c x 1024px slabs via cp.async double-buffer; weights duplicated
// (w,w) u64 in smem -> hot loop = uniform LDS.128 + 4 FFMA2 per (k, 2c).
// -------------------------------------------------------------------------
#define K1A_SMEM (K_ * CH_ * 8 + 2 * 16 * 1024 * 4)

__global__ __launch_bounds__(256)
void k1a_premask(const float* __restrict__ x, const float* __restrict__ Wm)
{
    extern __shared__ __align__(16) char smraw[];
    u64*   wdup = (u64*)smraw;                        // [K_][CH_]
    float* xb0  = (float*)(smraw + K_ * CH_ * 8);     // [16][1024]
    float* xb1  = xb0 + 16 * 1024;

    const int t   = threadIdx.x;
    const int h   = blockIdx.x >> 7;
    const int b   = (blockIdx.x >> 4) & 7;
    const int seg = blockIdx.x & 15;
    const int c0  = h * CH_;
    const int pb  = seg * 1024;

    const float* xg = x + ((size_t)b * C_ + c0) * HW_ + pb;

    // stage slab 0 (copies fly while we stage weights)
    {
        float* buf = xb0;
        #pragma unroll
        for (int it = 0; it < 16; it++) {
            const int idx = it * 256 + t;
            const int row = idx >> 8;
            const int chk = idx & 255;
            cp16(buf + row * 1024 + chk * 4, xg + (size_t)row * HW_ + chk * 4);
        }
        cp_commit();
    }

    // duplicate weights into smem
    for (int i = t; i < K_ * CH_; i += 256) {
        const float w = Wm[(i / CH_) * C_ + c0 + (i % CH_)];
        wdup[i] = pack2(w, w);
    }

    u64 acc[K_][2];
    #pragma unroll
    for (int k = 0; k < K_; k++) { acc[k][0] = 0ull; acc[k][1] = 0ull; }

    for (int s = 0; s < CH_ / 16; s++) {
        cp_wait_all();
        __syncthreads();
        if (s + 1 < CH_ / 16) {
            float* buf = ((s + 1) & 1) ? xb1 : xb0;
            #pragma unroll
            for (int it = 0; it < 16; it++) {
                const int idx = it * 256 + t;
                const int row = idx >> 8;
                const int chk = idx & 255;
                cp16(buf + row * 1024 + chk * 4,
                     xg + (size_t)((s + 1) * 16 + row) * HW_ + chk * 4);
            }
            cp_commit();
        }
        const float* fb = (s & 1) ? xb1 : xb0;
        #pragma unroll
        for (int c2 = 0; c2 < 8; c2++) {
            const float* xr0 = fb + (2 * c2) * 1024 + 4 * t;
            const u64 x0a = *(const u64*)(xr0);       // c even: px (0,1)
            const u64 x0b = *(const u64*)(xr0 + 2);   // c even: px (2,3)
            const u64 x1a = *(const u64*)(xr0 + 1024);
            const u64 x1b = *(const u64*)(xr0 + 1026);
            const int wc = s * 16 + 2 * c2;
            #pragma unroll
            for (int k = 0; k < K_; k++) {
                const ulonglong2 w = *(const ulonglong2*)&wdup[k * CH_ + wc];  // broadcast
                acc[k][0] = ffma2(x0a, w.x, acc[k][0]);
                acc[k][1] = ffma2(x0b, w.x, acc[k][1]);
                acc[k][0] = ffma2(x1a, w.y, acc[k][0]);
                acc[k][1] = ffma2(x1b, w.y, acc[k][1]);
            }
        }
    }

    float* dst = g_pm + (((size_t)h * B_ + b) * K_) * HW_ + pb + 4 * t;
    #pragma unroll
    for (int k = 0; k < K_; k++) {
        const float2 f0 = unpack2(acc[k][0]);
        const float2 f1 = unpack2(acc[k][1]);
        float4 v; v.x = f0.x; v.y = f0.y; v.z = f1.x; v.w = f1.y;
        *(float4*)(dst + (size_t)k * HW_) = v;
    }
}

// -------------------------------------------------------------------------
// k1b: partial[b,ch,k,c] = sum_{p in 512-px chunk} mask[b,k,p] * x[b,c,p]
// mask computed on the fly: sigmoid(pm0 + pm1 + bm).  Grid 256 = b x 32.
// 512 thr (thread = c). x staged 512c x 32px slabs via cp.async; lanes =
// px-pairs (x and mask both load directly as u64 pairs — no packing).
// -------------------------------------------------------------------------
#define K1B_SMEM (K_ * 512 * 4 + 2 * 512 * XROW * 4)

__global__ __launch_bounds__(512)
void k1b_pool(const float* __restrict__ x, const float* __restrict__ bm)
{
    extern __shared__ __align__(16) char smraw[];
    float* mask_s = (float*)smraw;                    // [K_][512]
    float* xb0    = (float*)(smraw + K_ * 512 * 4);   // [512][XROW]
    float* xb1    = xb0 + 512 * XROW;

    const int t  = threadIdx.x;
    const int b  = blockIdx.x >> 5;
    const int ch = blockIdx.x & 31;
    const int pb = ch * PXT;

    const float* xg = x + (size_t)b * C_ * HW_ + pb;

    // stage x slab 0
    {
        #pragma unroll
        for (int it = 0; it < 8; it++) {
            const int idx = it * 512 + t;
            const int row = idx >> 3;
            const int chk = idx & 7;
            cp16(xb0 + row * XROW + chk * 4, xg + (size_t)row * HW_ + chk * 4);
        }
        cp_commit();
    }

    // mask = sigmoid(pm0 + pm1 + bm) for this px chunk
    {
        const float* pm0 = g_pm + ((size_t)b * K_) * HW_ + pb;
        const float* pm1 = g_pm + (((size_t)B_ + b) * K_) * HW_ + pb;
        #pragma unroll
        for (int it = 0; it < 19; it++) {
            const int i  = it * 512 + t;
            const int k  = i >> 9;
            const int px = i & 511;
            const float pre = pm0[(size_t)k * HW_ + px] + pm1[(size_t)k * HW_ + px]
                            + __ldg(&bm[k]);
            mask_s[i] = 1.0f / (1.0f + __expf(-pre));
        }
    }

    u64 acc[K_];
    #pragma unroll
    for (int k = 0; k < K_; k++) acc[k] = 0ull;

    for (int s = 0; s < PXT / 32; s++) {
        cp_wait_all();
        __syncthreads();
        if (s + 1 < PXT / 32) {
            float* buf = ((s + 1) & 1) ? xb1 : xb0;
            #pragma unroll
            for (int it = 0; it < 8; it++) {
                const int idx = it * 512 + t;
                const int row = idx >> 3;
                const int chk = idx & 7;
                cp16(buf + row * XROW + chk * 4,
                     xg + (size_t)row * HW_ + (s + 1) * 32 + chk * 4);
            }
            cp_commit();
        }
        const float* fb = (s & 1) ? xb1 : xb0;
        const float* xr = fb + t * XROW;
        #pragma unroll
        for (int j2 = 0; j2 < 8; j2++) {
            const u64 xv0 = *(const u64*)(xr + j2 * 4);       // px pair (4j2, 4j2+1)
            const u64 xv1 = *(const u64*)(xr + j2 * 4 + 2);   // px pair (4j2+2, 4j2+3)
            #pragma unroll
            for (int k = 0; k < K_; k++) {
                const ulonglong2 mm = *(const ulonglong2*)&mask_s[k * 512 + s * 32 + j2 * 4];
                acc[k] = ffma2(xv0, mm.x, acc[k]);
                acc[k] = ffma2(xv1, mm.y, acc[k]);
            }
        }
    }

    float* dst = g_partial + ((size_t)b * NCHUNK + ch) * K_ * C_ + t;
    #pragma unroll
    for (int k = 0; k < K_; k++) {
        const float2 f = unpack2(acc[k]);
        dst[k * C_] = f.x + f.y;
    }
}

// -------------------------------------------------------------------------
// k2: deterministic reduction of partials -> class_feat / (h*w)
// -------------------------------------------------------------------------
__global__ __launch_bounds__(512)
void k2_reduce()
{
    const int bk = blockIdx.x;
    const int c  = threadIdx.x;
    const int b  = bk / K_;
    const int k  = bk % K_;

    const float* src = g_partial + ((size_t)b * NCHUNK * K_ + k) * C_ + c;
    float s = 0.f;
    #pragma unroll 8
    for (int ch = 0; ch < NCHUNK; ch++)
        s += src[(size_t)ch * K_ * C_];
    g_cf[(b * K_ + k) * C_ + c] = s * (1.0f / (float)HW_);
}

// -------------------------------------------------------------------------
// k3: filters[b,k,o] = sum_c Wf[k,o,c] * cf[b,k,c] + bf[k,o]
// Grid (19, 64), 256 thr; warp owns one o, lane owns c-chunk (coalesced Wf).
// -------------------------------------------------------------------------
__global__ __launch_bounds__(256)
void k3_filters(const float* __restrict__ Wf, const float* __restrict__ bf)
{
    __shared__ __align__(16) float cf_s[B_][C_ + 4];

    const int k    = blockIdx.x;
    const int og   = blockIdx.y;
    const int t    = threadIdx.x;
    const int w    = t >> 5;
    const int lane = t & 31;
    const int o    = og * 8 + w;

    for (int i = t; i < B_ * C_; i += 256) {
        const int bb = i >> 9;
        const int cc = i & 511;
        cf_s[bb][cc] = g_cf[(bb * K_ + k) * C_ + cc];
    }
    __syncthreads();

    const float* wrow = Wf + ((size_t)k * C_ + o) * C_;

    float acc[B_];
    #pragma unroll
    for (int bb = 0; bb < B_; bb++) acc[bb] = 0.f;

    #pragma unroll
    for (int ccq = 0; ccq < 4; ccq++) {
        const int cbase = ccq * 128 + lane * 4;
        const float4 wv = *(const float4*)(wrow + cbase);
        #pragma unroll
        for (int bb = 0; bb < B_; bb++) {
            const float4 f = *(const float4*)&cf_s[bb][cbase];
            acc[bb] = fmaf(wv.x, f.x,
                      fmaf(wv.y, f.y,
                      fmaf(wv.z, f.z,
                      fmaf(wv.w, f.w, acc[bb]))));
        }
    }

    #pragma unroll
    for (int off = 16; off >= 1; off >>= 1) {
        #pragma unroll
        for (int bb = 0; bb < B_; bb++)
            acc[bb] += __shfl_xor_sync(0xffffffffu, acc[bb], off);
    }

    if (lane < B_)
        g_filters[((size_t)lane * K_ + k) * C_ + o] = acc[lane] + bf[k * C_ + o];
}

// -------------------------------------------------------------------------
// k4: pred[b,k,p] = sum_c filters[b,k,c] * x[b,c,p]
// Grid 128 = b x 16 segs of 1024 px (single wave). 256 thr, 4 px/thread.
// Same cp.async skeleton as k1a with full C=512 dup-weight smem.
// -------------------------------------------------------------------------
#define K4_SMEM (K_ * C_ * 8 + 2 * 16 * 1024 * 4)

__global__ __launch_bounds__(256)
void k4_pred(const float* __restrict__ x, float* __restrict__ out)
{
    extern __shared__ __align__(16) char smraw[];
    u64*   wdup = (u64*)smraw;                        // [K_][C_]
    float* xb0  = (float*)(smraw + K_ * C_ * 8);      // [16][1024]
    float* xb1  = xb0 + 16 * 1024;

    const int t   = threadIdx.x;
    const int b   = blockIdx.x >> 4;
    const int seg = blockIdx.x & 15;
    const int pb  = seg * 1024;

    const float* xg = x + (size_t)b * C_ * HW_ + pb;

    // stage slab 0
    {
        #pragma unroll
        for (int it = 0; it < 16; it++) {
            const int idx = it * 256 + t;
            const int row = idx >> 8;
            const int chk = idx & 255;
            cp16(xb0 + row * 1024 + chk * 4, xg + (size_t)row * HW_ + chk * 4);
        }
        cp_commit();
    }

    // duplicate filters into smem
    {
        const float* fsrc = g_filters + (size_t)b * K_ * C_;
        for (int i = t; i < K_ * C_; i += 256) {
            const float w = fsrc[i];
            wdup[i] = pack2(w, w);
        }
    }

    u64 acc[K_][2];
    #pragma unroll
    for (int k = 0; k < K_; k++) { acc[k][0] = 0ull; acc[k][1] = 0ull; }

    for (int s = 0; s < C_ / 16; s++) {
        cp_wait_all();
        __syncthreads();
        if (s + 1 < C_ / 16) {
            float* buf = ((s + 1) & 1) ? xb1 : xb0;
            #pragma unroll
            for (int it = 0; it < 16; it++) {
                const int idx = it * 256 + t;
                const int row = idx >> 8;
                const int chk = idx & 255;
                cp16(buf + row * 1024 + chk * 4,
                     xg + (size_t)((s + 1) * 16 + row) * HW_ + chk * 4);
            }
            cp_commit();
        }
        const float* fb = (s & 1) ? xb1 : xb0;
        #pragma unroll
        for (int c2 = 0; c2 < 8; c2++) {
            const float* xr0 = fb + (2 * c2) * 1024 + 4 * t;
            const u64 x0a = *(const u64*)(xr0);
            const u64 x0b = *(const u64*)(xr0 + 2);
            const u64 x1a = *(const u64*)(xr0 + 1024);
            const u64 x1b = *(const u64*)(xr0 + 1026);
            const int wc = s * 16 + 2 * c2;
            #pragma unroll
            for (int k = 0; k < K_; k++) {
                const ulonglong2 w = *(const ulonglong2*)&wdup[k * C_ + wc];  // broadcast
                acc[k][0] = ffma2(x0a, w.x, acc[k][0]);
                acc[k][1] = ffma2(x0b, w.x, acc[k][1]);
                acc[k][0] = ffma2(x1a, w.y, acc[k][0]);
                acc[k][1] = ffma2(x1b, w.y, acc[k][1]);
            }
        }
    }

    float* ob = out + (size_t)b * K_ * HW_ + pb + 4 * t;
    #pragma unroll
    for (int k = 0; k < K_; k++) {
        const float2 f0 = unpack2(acc[k][0]);
        const float2 f1 = unpack2(acc[k][1]);
        float4 v; v.x = f0.x; v.y = f0.y; v.z = f1.x; v.w = f1.y;
        *(float4*)(ob + (size_t)k * HW_) = v;
    }
}

// -------------------------------------------------------------------------
extern "C" void kernel_launch(void* const* d_in, const int* in_sizes, int n_in,
                              void* d_out, int out_size)
{
    const float* x  = (const float*)d_in[0];
    const float* Wm = (const float*)d_in[1];
    const float* bm = (const float*)d_in[2];
    const float* Wf = (const float*)d_in[3];
    const float* bf = (const float*)d_in[4];
    float* out = (float*)d_out;

    cudaFuncSetAttribute(k1a_premask, cudaFuncAttributeMaxDynamicSharedMemorySize, K1A_SMEM);
    cudaFuncSetAttribute(k1b_pool,    cudaFuncAttributeMaxDynamicSharedMemorySize, K1B_SMEM);
    cudaFuncSetAttribute(k4_pred,     cudaFuncAttributeMaxDynamicSharedMemorySize, K4_SMEM);

    k1a_premask<<<256, 256, K1A_SMEM>>>(x, Wm);
    k1b_pool   <<<B_ * NCHUNK, 512, K1B_SMEM>>>(x, bm);
    k2_reduce  <<<B_ * K_, 512>>>();
    k3_filters <<<dim3(K_, 64), 256>>>(Wf, bf);
    k4_pred    <<<B_ * 16, 256, K4_SMEM>>>(x, out);
}

// round 10
// speedup vs baseline: 1.5351x; 1.0593x over previous
#include <cuda_runtime.h>
#include <math.h>
#include <stdint.h>

#define B_      8
#define C_      512
#define K_      19
#define HW_     16384
#define CH_     256           // c-half for k1a
#define NCHUNK  64            // px chunks (256 px) per image for pooling partials

typedef unsigned long long u64;

__device__ __forceinline__ u64 ffma2(u64 a, u64 b, u64 c) {
    u64 d; asm("fma.rn.f32x2 %0, %1, %2, %3;" : "=l"(d) : "l"(a), "l"(b), "l"(c)); return d;
}
__device__ __forceinline__ u64 pack2(float lo, float hi) {
    u64 d; asm("mov.b64 %0, {%1, %2};" : "=l"(d) : "f"(lo), "f"(hi)); return d;
}
__device__ __forceinline__ float2 unpack2(u64 v) {
    float2 r; asm("mov.b64 {%0, %1}, %2;" : "=f"(r.x), "=f"(r.y) : "l"(v)); return r;
}
__device__ __forceinline__ void cp16(void* smem_dst, const void* gmem_src) {
    unsigned sa = (unsigned)__cvta_generic_to_shared(smem_dst);
    asm volatile("cp.async.cg.shared.global [%0], [%1], 16;" :: "r"(sa), "l"(gmem_src));
}
__device__ __forceinline__ void cp_commit() { asm volatile("cp.async.commit_group;"); }
__device__ __forceinline__ void cp_wait_all() { asm volatile("cp.async.wait_group 0;"); }

__device__ __forceinline__ uint32_t f2tf(float f) {
    uint32_t u; asm("cvt.rna.tf32.f32 %0, %1;" : "=r"(u) : "f"(f)); return u;
}
__device__ __forceinline__ void mma_tf32(float* d,
        uint32_t a0, uint32_t a1, uint32_t a2, uint32_t a3,
        uint32_t b0, uint32_t b1) {
    asm volatile("mma.sync.aligned.m16n8k8.row.col.f32.tf32.tf32.f32 "
        "{%0,%1,%2,%3}, {%4,%5,%6,%7}, {%8,%9}, {%0,%1,%2,%3};"
        : "+f"(d[0]), "+f"(d[1]), "+f"(d[2]), "+f"(d[3])
        : "r"(a0), "r"(a1), "r"(a2), "r"(a3), "r"(b0), "r"(b1));
}

// Scratch (device globals — no allocation allowed)
__device__ float g_pm[2 * B_ * K_ * HW_];             // pre-mask partials (2 c-halves)
__device__ float g_partial[B_ * NCHUNK * K_ * C_];    // pooling partials
__device__ float g_cf[B_ * K_ * C_];
__device__ float g_filters[B_ * K_ * C_];

// -------------------------------------------------------------------------
// k1a (fp32 FFMA2, exact — sigmoid path is tf32-unsafe):
// pm[h,b,k,p] = sum_{c in half} Wm[k,c] x[b,c,p]
// -------------------------------------------------------------------------
#define K1A_SMEM (K_ * CH_ * 8 + 2 * 16 * 1024 * 4)

__global__ __launch_bounds__(256)
void k1a_premask(const float* __restrict__ x, const float* __restrict__ Wm)
{
    extern __shared__ __align__(16) char smraw[];
    u64*   wdup = (u64*)smraw;                        // [K_][CH_]
    float* xb0  = (float*)(smraw + K_ * CH_ * 8);     // [16][1024]
    float* xb1  = xb0 + 16 * 1024;

    const int t   = threadIdx.x;
    const int h   = blockIdx.x >> 7;
    const int b   = (blockIdx.x >> 4) & 7;
    const int seg = blockIdx.x & 15;
    const int c0  = h * CH_;
    const int pb  = seg * 1024;

    const float* xg = x + ((size_t)b * C_ + c0) * HW_ + pb;

    {
        #pragma unroll
        for (int it = 0; it < 16; it++) {
            const int idx = it * 256 + t;
            const int row = idx >> 8;
            const int chk = idx & 255;
            cp16(xb0 + row * 1024 + chk * 4, xg + (size_t)row * HW_ + chk * 4);
        }
        cp_commit();
    }

    for (int i = t; i < K_ * CH_; i += 256) {
        const float w = Wm[(i / CH_) * C_ + c0 + (i % CH_)];
        wdup[i] = pack2(w, w);
    }

    u64 acc[K_][2];
    #pragma unroll
    for (int k = 0; k < K_; k++) { acc[k][0] = 0ull; acc[k][1] = 0ull; }

    for (int s = 0; s < CH_ / 16; s++) {
        cp_wait_all();
        __syncthreads();
        if (s + 1 < CH_ / 16) {
            float* buf = ((s + 1) & 1) ? xb1 : xb0;
            #pragma unroll
            for (int it = 0; it < 16; it++) {
                const int idx = it * 256 + t;
                const int row = idx >> 8;
                const int chk = idx & 255;
                cp16(buf + row * 1024 + chk * 4,
                     xg + (size_t)((s + 1) * 16 + row) * HW_ + chk * 4);
            }
            cp_commit();
        }
        const float* fb = (s & 1) ? xb1 : xb0;
        #pragma unroll
        for (int c2 = 0; c2 < 8; c2++) {
            const float* xr0 = fb + (2 * c2) * 1024 + 4 * t;
            const u64 x0a = *(const u64*)(xr0);
            const u64 x0b = *(const u64*)(xr0 + 2);
            const u64 x1a = *(const u64*)(xr0 + 1024);
            const u64 x1b = *(const u64*)(xr0 + 1026);
            const int wc = s * 16 + 2 * c2;
            #pragma unroll
            for (int k = 0; k < K_; k++) {
                const ulonglong2 w = *(const ulonglong2*)&wdup[k * CH_ + wc];
                acc[k][0] = ffma2(x0a, w.x, acc[k][0]);
                acc[k][1] = ffma2(x0b, w.x, acc[k][1]);
                acc[k][0] = ffma2(x1a, w.y, acc[k][0]);
                acc[k][1] = ffma2(x1b, w.y, acc[k][1]);
            }
        }
    }

    float* dst = g_pm + (((size_t)h * B_ + b) * K_) * HW_ + pb + 4 * t;
    #pragma unroll
    for (int k = 0; k < K_; k++) {
        const float2 f0 = unpack2(acc[k][0]);
        const float2 f1 = unpack2(acc[k][1]);
        float4 v; v.x = f0.x; v.y = f0.y; v.z = f1.x; v.w = f1.y;
        *(float4*)(dst + (size_t)k * HW_) = v;
    }
}

// -------------------------------------------------------------------------
// k1b (tf32 MMA): partialT[c][k] = sum_px x[c,px] * mask[px,k] per (b, chunk).
// A = x slab [c][px] row-major (m=c, k-dim=px), B = mask^T [px][24] col frag.
// Mask computed once per chunk: sigmoid(pm0+pm1+bm), tf32, stored [px][24].
// Grid 512 = b x 64 chunks of 256 px. 256 thr (8 warps): warp = 4 m-tiles x 3 n.
// -------------------------------------------------------------------------
#define K1B_SMEM (256 * 24 * 4 + 2 * 512 * 20 * 4)   // 24576 + 81920 = 106496

__global__ __launch_bounds__(256)
void k1b_mma(const float* __restrict__ x, const float* __restrict__ bm)
{
    extern __shared__ __align__(16) char sm[];
    uint32_t* Mt  = (uint32_t*)sm;                 // [256 px][24]
    float*    xb0 = (float*)(sm + 24576);          // [512][20]
    float*    xb1 = xb0 + 512 * 20;

    const int t   = threadIdx.x;
    const int b   = blockIdx.x >> 6;
    const int ch  = blockIdx.x & 63;
    const int pxb = ch * 256;

    const float* xg = x + (size_t)b * C_ * HW_ + pxb;

    // stage x slab 0 (px 0..15)
    {
        #pragma unroll
        for (int it = 0; it < 8; it++) {
            const int idx = it * 256 + t;
            const int row = idx >> 2;
            const int chk = idx & 3;
            cp16(xb0 + row * 20 + chk * 4, xg + (size_t)row * HW_ + chk * 4);
        }
        cp_commit();
    }

    // mask: sigmoid(pm0+pm1+bm) -> tf32, transposed [px][24]
    {
        const float* pm0 = g_pm + ((size_t)b * K_) * HW_ + pxb;
        const float* pm1 = g_pm + (((size_t)B_ + b) * K_) * HW_ + pxb;
        for (int i = t; i < 24 * 256; i += 256) {
            const int n  = i >> 8;
            const int px = i & 255;
            float v = 0.f;
            if (n < K_) {
                const float pre = pm0[(size_t)n * HW_ + px] + pm1[(size_t)n * HW_ + px]
                                + __ldg(&bm[n]);
                v = 1.0f / (1.0f + __expf(-pre));
            }
            Mt[px * 24 + n] = f2tf(v);
        }
    }

    const int w = t >> 5, lane = t & 31, g = lane >> 2, tg = lane & 3;

    float acc[4][3][4];
    #pragma unroll
    for (int j = 0; j < 4; j++)
        #pragma unroll
        for (int nt = 0; nt < 3; nt++)
            #pragma unroll
            for (int r = 0; r < 4; r++) acc[j][nt][r] = 0.f;

    for (int s = 0; s < 16; s++) {
        cp_wait_all();
        __syncthreads();
        if (s + 1 < 16) {
            float* buf = ((s + 1) & 1) ? xb1 : xb0;
            #pragma unroll
            for (int it = 0; it < 8; it++) {
                const int idx = it * 256 + t;
                const int row = idx >> 2;
                const int chk = idx & 3;
                cp16(buf + row * 20 + chk * 4,
                     xg + (size_t)row * HW_ + (s + 1) * 16 + chk * 4);
            }
            cp_commit();
        }
        const float* xs = (s & 1) ? xb1 : xb0;
        #pragma unroll
        for (int half = 0; half < 2; half++) {
            const int pl  = half * 8;
            const int pxk = s * 16 + pl;
            uint32_t b0[3], b1[3];
            const uint32_t* mp  = Mt + (pxk + tg) * 24 + g;
            const uint32_t* mp2 = mp + 4 * 24;
            #pragma unroll
            for (int nt = 0; nt < 3; nt++) { b0[nt] = mp[nt * 8]; b1[nt] = mp2[nt * 8]; }
            #pragma unroll
            for (int j = 0; j < 4; j++) {
                const int c0 = w * 64 + j * 16;
                const float* ap = xs + (c0 + g) * 20 + pl + tg;
                const uint32_t a0 = f2tf(ap[0]);
                const uint32_t a1 = f2tf(ap[8 * 20]);
                const uint32_t a2 = f2tf(ap[4]);
                const uint32_t a3 = f2tf(ap[8 * 20 + 4]);
                #pragma unroll
                for (int nt = 0; nt < 3; nt++)
                    mma_tf32(acc[j][nt], a0, a1, a2, a3, b0[nt], b1[nt]);
            }
        }
    }

    float* dst = g_partial + ((size_t)(b * NCHUNK + ch)) * K_ * C_;
    #pragma unroll
    for (int j = 0; j < 4; j++) {
        const int c = w * 64 + j * 16 + g;
        #pragma unroll
        for (int nt = 0; nt < 3; nt++) {
            const int n = nt * 8 + 2 * tg;
            if (n < K_) {
                dst[n * C_ + c]     = acc[j][nt][0];
                dst[n * C_ + c + 8] = acc[j][nt][2];
            }
            if (n + 1 < K_) {
                dst[(n + 1) * C_ + c]     = acc[j][nt][1];
                dst[(n + 1) * C_ + c + 8] = acc[j][nt][3];
            }
        }
    }
}

// -------------------------------------------------------------------------
// k2: deterministic reduction of partials -> class_feat / (h*w)
// -------------------------------------------------------------------------
__global__ __launch_bounds__(512)
void k2_reduce()
{
    const int bk = blockIdx.x;
    const int c  = threadIdx.x;
    const int b  = bk / K_;
    const int k  = bk % K_;

    const float* src = g_partial + ((size_t)b * NCHUNK * K_ + k) * C_ + c;
    float s = 0.f;
    #pragma unroll 8
    for (int ch = 0; ch < NCHUNK; ch++)
        s += src[(size_t)ch * K_ * C_];
    g_cf[(b * K_ + k) * C_ + c] = s * (1.0f / (float)HW_);
}

// -------------------------------------------------------------------------
// k3: filters[b,k,o] = sum_c Wf[k,o,c] * cf[b,k,c] + bf[k,o]
// -------------------------------------------------------------------------
__global__ __launch_bounds__(256)
void k3_filters(const float* __restrict__ Wf, const float* __restrict__ bf)
{
    __shared__ __align__(16) float cf_s[B_][C_ + 4];

    const int k    = blockIdx.x;
    const int og   = blockIdx.y;
    const int t    = threadIdx.x;
    const int w    = t >> 5;
    const int lane = t & 31;
    const int o    = og * 8 + w;

    for (int i = t; i < B_ * C_; i += 256) {
        const int bb = i >> 9;
        const int cc = i & 511;
        cf_s[bb][cc] = g_cf[(bb * K_ + k) * C_ + cc];
    }
    __syncthreads();

    const float* wrow = Wf + ((size_t)k * C_ + o) * C_;

    float acc[B_];
    #pragma unroll
    for (int bb = 0; bb < B_; bb++) acc[bb] = 0.f;

    #pragma unroll
    for (int ccq = 0; ccq < 4; ccq++) {
        const int cbase = ccq * 128 + lane * 4;
        const float4 wv = *(const float4*)(wrow + cbase);
        #pragma unroll
        for (int bb = 0; bb < B_; bb++) {
            const float4 f = *(const float4*)&cf_s[bb][cbase];
            acc[bb] = fmaf(wv.x, f.x,
                      fmaf(wv.y, f.y,
                      fmaf(wv.z, f.z,
                      fmaf(wv.w, f.w, acc[bb]))));
        }
    }

    #pragma unroll
    for (int off = 16; off >= 1; off >>= 1) {
        #pragma unroll
        for (int bb = 0; bb < B_; bb++)
            acc[bb] += __shfl_xor_sync(0xffffffffu, acc[bb], off);
    }

    if (lane < B_)
        g_filters[((size_t)lane * K_ + k) * C_ + o] = acc[lane] + bf[k * C_ + o];
}

// -------------------------------------------------------------------------
// k4 (tf32 MMA): pred[b,k,p] = sum_c filters[b,k,c] * x[b,c,p]
// A = x^T tile (m=px, k-dim=c) from slab [16 c][136], B = filters^T [c][24].
// Grid 1024 = b x 128 segs of 128 px. 256 thr: warp = one 16-px m-tile x 3 n.
// -------------------------------------------------------------------------
#define K4_SMEM (24 * C_ * 4 + 2 * 16 * 136 * 4)     // 49152 + 17408 = 66560

__global__ __launch_bounds__(256)
void k4_mma(const float* __restrict__ x, float* __restrict__ out)
{
    extern __shared__ __align__(16) char sm[];
    uint32_t* Wt  = (uint32_t*)sm;                 // [512 c][24]
    float*    xb0 = (float*)(sm + 24 * C_ * 4);    // [16][136]
    float*    xb1 = xb0 + 16 * 136;

    const int t   = threadIdx.x;
    const int b   = blockIdx.x >> 7;
    const int seg = blockIdx.x & 127;
    const int pb  = seg * 128;

    const float* xg = x + (size_t)b * C_ * HW_ + pb;

    // stage x slab 0 (c 0..15)
    {
        #pragma unroll
        for (int it = 0; it < 2; it++) {
            const int idx = it * 256 + t;
            const int row = idx >> 5;
            const int chk = idx & 31;
            cp16(xb0 + row * 136 + chk * 4, xg + (size_t)row * HW_ + chk * 4);
        }
        cp_commit();
    }

    // stage filters^T as tf32 [c][24]
    {
        const float* wsrc = g_filters + (size_t)b * K_ * C_;
        for (int i = t; i < 24 * C_; i += 256) {
            const int c = i / 24;
            const int n = i - c * 24;
            const float v = (n < K_) ? wsrc[n * C_ + c] : 0.f;
            Wt[c * 24 + n] = f2tf(v);
        }
    }

    const int w = t >> 5, lane = t & 31, g = lane >> 2, tg = lane & 3;
    const int px0 = w * 16;

    float acc[3][4];
    #pragma unroll
    for (int nt = 0; nt < 3; nt++)
        #pragma unroll
        for (int r = 0; r < 4; r++) acc[nt][r] = 0.f;

    for (int s = 0; s < 32; s++) {
        cp_wait_all();
        __syncthreads();
        if (s + 1 < 32) {
            float* buf = ((s + 1) & 1) ? xb1 : xb0;
            #pragma unroll
            for (int it = 0; it < 2; it++) {
                const int idx = it * 256 + t;
                const int row = idx >> 5;
                const int chk = idx & 31;
                cp16(buf + row * 136 + chk * 4,
                     xg + (size_t)((s + 1) * 16 + row) * HW_ + chk * 4);
            }
            cp_commit();
        }
        const float* xs = (s & 1) ? xb1 : xb0;
        #pragma unroll
        for (int half = 0; half < 2; half++) {
            const int cl = half * 8;
            const float* ap = xs + (cl + tg) * 136 + px0 + g;
            const uint32_t a0 = f2tf(ap[0]);
            const uint32_t a1 = f2tf(ap[8]);
            const uint32_t a2 = f2tf(ap[4 * 136]);
            const uint32_t a3 = f2tf(ap[4 * 136 + 8]);
            const uint32_t* bp  = Wt + (s * 16 + cl + tg) * 24 + g;
            const uint32_t* bp2 = bp + 4 * 24;
            #pragma unroll
            for (int nt = 0; nt < 3; nt++)
                mma_tf32(acc[nt], a0, a1, a2, a3, bp[nt * 8], bp2[nt * 8]);
        }
    }

    const int px = pb + px0 + g;
    #pragma unroll
    for (int nt = 0; nt < 3; nt++) {
        const int n = nt * 8 + 2 * tg;
        if (n < K_) {
            float* o = out + ((size_t)b * K_ + n) * HW_ + px;
            o[0] = acc[nt][0];
            o[8] = acc[nt][2];
        }
        if (n + 1 < K_) {
            float* o = out + ((size_t)b * K_ + n + 1) * HW_ + px;
            o[0] = acc[nt][1];
            o[8] = acc[nt][3];
        }
    }
}

// -------------------------------------------------------------------------
extern "C" void kernel_launch(void* const* d_in, const int* in_sizes, int n_in,
                              void* d_out, int out_size)
{
    const float* x  = (const float*)d_in[0];
    const float* Wm = (const float*)d_in[1];
    const float* bm = (const float*)d_in[2];
    const float* Wf = (const float*)d_in[3];
    const float* bf = (const float*)d_in[4];
    float* out = (float*)d_out;

    cudaFuncSetAttribute(k1a_premask, cudaFuncAttributeMaxDynamicSharedMemorySize, K1A_SMEM);
    cudaFuncSetAttribute(k1b_mma,     cudaFuncAttributeMaxDynamicSharedMemorySize, K1B_SMEM);
    cudaFuncSetAttribute(k4_mma,      cudaFuncAttributeMaxDynamicSharedMemorySize, K4_SMEM);

    k1a_premask<<<256, 256, K1A_SMEM>>>(x, Wm);
    k1b_mma    <<<B_ * NCHUNK, 256, K1B_SMEM>>>(x, bm);
    k2_reduce  <<<B_ * K_, 512>>>();
    k3_filters <<<dim3(K_, 64), 256>>>(Wf, bf);
    k4_mma     <<<B_ * 128, 256, K4_SMEM>>>(x, out);
}

// round 12
// speedup vs baseline: 1.6649x; 1.0846x over previous
#include <cuda_runtime.h>
#include <math.h>
#include <stdint.h>

#define B_      8
#define C_      512
#define K_      19
#define HW_     16384
#define NCHUNK  256           // 64-px chunks per image (fused k1)
#define SX      72            // k1 x smem row stride (floats), conflict-free
#define SX4     136           // k4 x smem row stride (floats)

typedef unsigned long long u64;

__device__ __forceinline__ void cp16(void* smem_dst, const void* gmem_src) {
    unsigned sa = (unsigned)__cvta_generic_to_shared(smem_dst);
    asm volatile("cp.async.cg.shared.global [%0], [%1], 16;" :: "r"(sa), "l"(gmem_src));
}
__device__ __forceinline__ void cp_commit() { asm volatile("cp.async.commit_group;" ::: "memory"); }
__device__ __forceinline__ void cp_wait_all() { asm volatile("cp.async.wait_group 0;" ::: "memory"); }
__device__ __forceinline__ void cp_waitN(int i) {   // wait until <= (6-2i) groups pending
    switch (i) {
        case 0: asm volatile("cp.async.wait_group 6;" ::: "memory"); break;
        case 1: asm volatile("cp.async.wait_group 4;" ::: "memory"); break;
        case 2: asm volatile("cp.async.wait_group 2;" ::: "memory"); break;
        default: asm volatile("cp.async.wait_group 0;" ::: "memory"); break;
    }
}
__device__ __forceinline__ uint32_t f2tf(float f) {
    uint32_t u; asm("cvt.rna.tf32.f32 %0, %1;" : "=r"(u) : "f"(f)); return u;
}
__device__ __forceinline__ void mma_tf32(float* d,
        uint32_t a0, uint32_t a1, uint32_t a2, uint32_t a3,
        uint32_t b0, uint32_t b1) {
    asm volatile("mma.sync.aligned.m16n8k8.row.col.f32.tf32.tf32.f32 "
        "{%0,%1,%2,%3}, {%4,%5,%6,%7}, {%8,%9}, {%0,%1,%2,%3};"
        : "+f"(d[0]), "+f"(d[1]), "+f"(d[2]), "+f"(d[3])
        : "r"(a0), "r"(a1), "r"(a2), "r"(a3), "r"(b0), "r"(b1));
}

// Scratch (device globals — no allocation allowed)
__device__ float g_partial[B_ * NCHUNK * K_ * C_];    // ~80 MB pooling partials
__device__ float g_cf[B_ * K_ * C_];
__device__ float g_filters[B_ * K_ * C_];

// =========================================================================
// k1_fused: per (b, 64-px chunk):
//   x chunk [512 c][64 px] resident in smem (one gmem read serves BOTH phases)
//   premask = Wm @ x  via SPLIT-tf32 (3 MMAs: hh + hl + lh -> ~fp32 exact)
//   mask = sigmoid(premask + bm)  (tf32)
//   partial[k][c] = x @ mask^T    via single tf32 MMA
// Grid 2048 = b x 256 chunks, 256 thr (8 warps), 1 block/SM (210 KB smem).
// Premask: warp = (m-tile mt=w&3, c-half=w>>2); slabs staged interleaved
// 0,4,1,5,2,6,3,7 so both halves always have a ready slab.
// =========================================================================
#define K1_X_BYTES   (C_ * SX * 4)            // 147456
#define K1_W_OFF     K1_X_BYTES
#define K1_W_BYTES   (C_ * 24 * 4)            // 49152
#define K1_PM_OFF    (K1_W_OFF + K1_W_BYTES)  // 196608
#define K1_PM_BYTES  (2 * 64 * 24 * 4)        // 12288
#define K1_MT_OFF    (K1_PM_OFF + K1_PM_BYTES)
#define K1_SMEM      (K1_MT_OFF + 64 * 24 * 4)  // 215040

__global__ __launch_bounds__(256)
void k1_fused(const float* __restrict__ x,
              const float* __restrict__ Wm,
              const float* __restrict__ bm)
{
    extern __shared__ __align__(16) char sm[];
    float*    xs  = (float*)sm;                  // [512 c][SX]
    float*    Wt  = (float*)(sm + K1_W_OFF);     // [512 c][24]  fp32
    float*    pmh = (float*)(sm + K1_PM_OFF);    // [2 half][64 px][24]
    uint32_t* Mt  = (uint32_t*)(sm + K1_MT_OFF); // [64 px][24]  tf32

    const int t   = threadIdx.x;
    const int b   = blockIdx.x >> 8;
    const int ch  = blockIdx.x & 255;
    const int pxb = ch * 64;

    const float* xg = x + (size_t)b * C_ * HW_ + pxb;

    // ---- stage ALL x: 8 slabs of 64 c, interleaved order, commit each ----
    const int order[8] = {0, 4, 1, 5, 2, 6, 3, 7};
    #pragma unroll
    for (int si = 0; si < 8; si++) {
        const int s = order[si];
        #pragma unroll
        for (int it = 0; it < 4; it++) {
            const int idx = it * 256 + t;
            const int row = s * 64 + (idx >> 4);
            const int chk = idx & 15;
            cp16(xs + row * SX + chk * 4, xg + (size_t)row * HW_ + chk * 4);
        }
        cp_commit();
    }

    // ---- stage Wm^T fp32 [c][24], coalesced per n ----
    for (int c = t; c < C_; c += 256) {
        #pragma unroll
        for (int n = 0; n < K_; n++) Wt[c * 24 + n] = Wm[n * C_ + c];
        #pragma unroll
        for (int n = K_; n < 24; n++) Wt[c * 24 + n] = 0.f;
    }

    const int w = t >> 5, lane = t & 31, g = lane >> 2, tg = lane & 3;
    const int mt = w & 3, half = w >> 2;
    const int px0 = mt * 16;

    // ---- phase 1: premask via split-tf32 MMA ----
    float accP[3][4];
    #pragma unroll
    for (int nt = 0; nt < 3; nt++)
        #pragma unroll
        for (int r = 0; r < 4; r++) accP[nt][r] = 0.f;

    #pragma unroll
    for (int i = 0; i < 4; i++) {
        cp_waitN(i);             // first 2(i+1) slabs done
        __syncthreads();
        const int slab = half * 4 + i;
        #pragma unroll
        for (int ks = 0; ks < 8; ks++) {
            const int c = slab * 64 + ks * 8;
            const float* ap = xs + (c + tg) * SX + px0 + g;
            const float v0 = ap[0], v1 = ap[8], v2 = ap[4 * SX], v3 = ap[4 * SX + 8];
            const uint32_t h0 = f2tf(v0), h1 = f2tf(v1), h2 = f2tf(v2), h3 = f2tf(v3);
            const uint32_t l0 = f2tf(v0 - __uint_as_float(h0));
            const uint32_t l1 = f2tf(v1 - __uint_as_float(h1));
            const uint32_t l2 = f2tf(v2 - __uint_as_float(h2));
            const uint32_t l3 = f2tf(v3 - __uint_as_float(h3));
            #pragma unroll
            for (int nt = 0; nt < 3; nt++) {
                const float bw0 = Wt[(c + tg) * 24 + nt * 8 + g];
                const float bw1 = Wt[(c + 4 + tg) * 24 + nt * 8 + g];
                const uint32_t bh0 = f2tf(bw0), bh1 = f2tf(bw1);
                const uint32_t bl0 = f2tf(bw0 - __uint_as_float(bh0));
                const uint32_t bl1 = f2tf(bw1 - __uint_as_float(bh1));
                mma_tf32(accP[nt], h0, h1, h2, h3, bh0, bh1);
                mma_tf32(accP[nt], h0, h1, h2, h3, bl0, bl1);
                mma_tf32(accP[nt], l0, l1, l2, l3, bh0, bh1);
            }
        }
    }

    // write premask half-partials
    #pragma unroll
    for (int nt = 0; nt < 3; nt++) {
        const int n = nt * 8 + 2 * tg;
        pmh[(half * 64 + px0 + g) * 24 + n]         = accP[nt][0];
        pmh[(half * 64 + px0 + g) * 24 + n + 1]     = accP[nt][1];
        pmh[(half * 64 + px0 + g + 8) * 24 + n]     = accP[nt][2];
        pmh[(half * 64 + px0 + g + 8) * 24 + n + 1] = accP[nt][3];
    }
    __syncthreads();

    // ---- phase 2: sigmoid -> Mt tf32 [px][24] ----
    {
        const int px = t & 63;
        const int nb = (t >> 6) * 6;
        #pragma unroll
        for (int j = 0; j < 6; j++) {
            const int n = nb + j;
            float m = 0.f;
            if (n < K_) {
                const float pre = pmh[px * 24 + n] + pmh[(64 + px) * 24 + n]
                                + __ldg(&bm[n]);
                m = 1.0f / (1.0f + __expf(-pre));
            }
            Mt[px * 24 + n] = f2tf(m);
        }
    }
    __syncthreads();

    // ---- phase 3: pooling partial[k][c] via tf32 MMA (m=c, n=k, kdim=px) ----
    float acc2[4][3][4];
    #pragma unroll
    for (int j = 0; j < 4; j++)
        #pragma unroll
        for (int nt = 0; nt < 3; nt++)
            #pragma unroll
            for (int r = 0; r < 4; r++) acc2[j][nt][r] = 0.f;

    #pragma unroll
    for (int ks = 0; ks < 8; ks++) {
        const int pl = ks * 8;
        uint32_t b0[3], b1[3];
        const uint32_t* mp  = Mt + (pl + tg) * 24 + g;
        const uint32_t* mp2 = mp + 4 * 24;
        #pragma unroll
        for (int nt = 0; nt < 3; nt++) { b0[nt] = mp[nt * 8]; b1[nt] = mp2[nt * 8]; }
        #pragma unroll
        for (int j = 0; j < 4; j++) {
            const int c0 = w * 64 + j * 16;
            const float* ap = xs + (c0 + g) * SX + pl + tg;
            const uint32_t a0 = f2tf(ap[0]);
            const uint32_t a1 = f2tf(ap[8 * SX]);
            const uint32_t a2 = f2tf(ap[4]);
            const uint32_t a3 = f2tf(ap[8 * SX + 4]);
            #pragma unroll
            for (int nt = 0; nt < 3; nt++)
                mma_tf32(acc2[j][nt], a0, a1, a2, a3, b0[nt], b1[nt]);
        }
    }

    float* dst = g_partial + ((size_t)(b * NCHUNK + ch)) * K_ * C_;
    #pragma unroll
    for (int j = 0; j < 4; j++) {
        const int c = w * 64 + j * 16 + g;
        #pragma unroll
        for (int nt = 0; nt < 3; nt++) {
            const int n = nt * 8 + 2 * tg;
            if (n < K_) {
                dst[n * C_ + c]     = acc2[j][nt][0];
                dst[n * C_ + c + 8] = acc2[j][nt][2];
            }
            if (n + 1 < K_) {
                dst[(n + 1) * C_ + c]     = acc2[j][nt][1];
                dst[(n + 1) * C_ + c + 8] = acc2[j][nt][3];
            }
        }
    }
}

// -------------------------------------------------------------------------
// k2: deterministic reduction of 256 partials -> class_feat / (h*w)
// -------------------------------------------------------------------------
__global__ __launch_bounds__(512)
void k2_reduce()
{
    const int bk = blockIdx.x;
    const int c  = threadIdx.x;
    const int b  = bk / K_;
    const int k  = bk % K_;

    const float* src = g_partial + ((size_t)b * NCHUNK * K_ + k) * C_ + c;
    float s = 0.f;
    #pragma unroll 8
    for (int ch = 0; ch < NCHUNK; ch++)
        s += src[(size_t)ch * K_ * C_];
    g_cf[(b * K_ + k) * C_ + c] = s * (1.0f / (float)HW_);
}

// -------------------------------------------------------------------------
// k3: filters[b,k,o] = sum_c Wf[k,o,c] * cf[b,k,c] + bf[k,o]
// -------------------------------------------------------------------------
__global__ __launch_bounds__(256)
void k3_filters(const float* __restrict__ Wf, const float* __restrict__ bf)
{
    __shared__ __align__(16) float cf_s[B_][C_ + 4];

    const int k    = blockIdx.x;
    const int og   = blockIdx.y;
    const int t    = threadIdx.x;
    const int w    = t >> 5;
    const int lane = t & 31;
    const int o    = og * 8 + w;

    for (int i = t; i < B_ * C_; i += 256) {
        const int bb = i >> 9;
        const int cc = i & 511;
        cf_s[bb][cc] = g_cf[(bb * K_ + k) * C_ + cc];
    }
    __syncthreads();

    const float* wrow = Wf + ((size_t)k * C_ + o) * C_;

    float acc[B_];
    #pragma unroll
    for (int bb = 0; bb < B_; bb++) acc[bb] = 0.f;

    #pragma unroll
    for (int ccq = 0; ccq < 4; ccq++) {
        const int cbase = ccq * 128 + lane * 4;
        const float4 wv = *(const float4*)(wrow + cbase);
        #pragma unroll
        for (int bb = 0; bb < B_; bb++) {
            const float4 f = *(const float4*)&cf_s[bb][cbase];
            acc[bb] = fmaf(wv.x, f.x,
                      fmaf(wv.y, f.y,
                      fmaf(wv.z, f.z,
                      fmaf(wv.w, f.w, acc[bb]))));
        }
    }

    #pragma unroll
    for (int off = 16; off >= 1; off >>= 1) {
        #pragma unroll
        for (int bb = 0; bb < B_; bb++)
            acc[bb] += __shfl_xor_sync(0xffffffffu, acc[bb], off);
    }

    if (lane < B_)
        g_filters[((size_t)lane * K_ + k) * C_ + o] = acc[lane] + bf[k * C_ + o];
}

// -------------------------------------------------------------------------
// k4 (tf32 MMA): pred[b,k,p] = sum_c filters[b,k,c] * x[b,c,p]
// Grid 1024 = b x 128 segs of 128 px. Slabs of 32 c (16 KB) -> 16 barriers.
// Wt staged COALESCED (per-n contiguous reads).
// -------------------------------------------------------------------------
#define K4_SMEM (24 * C_ * 4 + 2 * 32 * SX4 * 4)   // 49152 + 34816 = 83968

__global__ __launch_bounds__(256)
void k4_mma(const float* __restrict__ x, float* __restrict__ out)
{
    extern __shared__ __align__(16) char sm[];
    uint32_t* Wt  = (uint32_t*)sm;                 // [512 c][24] tf32
    float*    xb0 = (float*)(sm + 24 * C_ * 4);    // [32 c][SX4]
    float*    xb1 = xb0 + 32 * SX4;

    const int t   = threadIdx.x;
    const int b   = blockIdx.x >> 7;
    const int seg = blockIdx.x & 127;
    const int pb  = seg * 128;

    const float* xg = x + (size_t)b * C_ * HW_ + pb;

    // stage x slab 0 (c 0..31)
    {
        #pragma unroll
        for (int it = 0; it < 4; it++) {
            const int idx = it * 256 + t;
            const int row = idx >> 5;
            const int chk = idx & 31;
            cp16(xb0 + row * SX4 + chk * 4, xg + (size_t)row * HW_ + chk * 4);
        }
        cp_commit();
    }

    // stage filters^T tf32 [c][24], coalesced per n
    {
        const float* wsrc = g_filters + (size_t)b * K_ * C_;
        for (int c = t; c < C_; c += 256) {
            #pragma unroll
            for (int n = 0; n < K_; n++) Wt[c * 24 + n] = f2tf(wsrc[n * C_ + c]);
            #pragma unroll
            for (int n = K_; n < 24; n++) Wt[c * 24 + n] = 0u;
        }
    }

    const int w = t >> 5, lane = t & 31, g = lane >> 2, tg = lane & 3;
    const int px0 = w * 16;

    float acc[3][4];
    #pragma unroll
    for (int nt = 0; nt < 3; nt++)
        #pragma unroll
        for (int r = 0; r < 4; r++) acc[nt][r] = 0.f;

    for (int s = 0; s < 16; s++) {
        cp_wait_all();
        __syncthreads();
        if (s + 1 < 16) {
            float* buf = ((s + 1) & 1) ? xb1 : xb0;
            #pragma unroll
            for (int it = 0; it < 4; it++) {
                const int idx = it * 256 + t;
                const int row = idx >> 5;
                const int chk = idx & 31;
                cp16(buf + row * SX4 + chk * 4,
                     xg + (size_t)((s + 1) * 32 + row) * HW_ + chk * 4);
            }
            cp_commit();
        }
        const float* xs = (s & 1) ? xb1 : xb0;
        #pragma unroll
        for (int kk = 0; kk < 4; kk++) {
            const int cl = kk * 8;
            const float* ap = xs + (cl + tg) * SX4 + px0 + g;
            const uint32_t a0 = f2tf(ap[0]);
            const uint32_t a1 = f2tf(ap[8]);
            const uint32_t a2 = f2tf(ap[4 * SX4]);
            const uint32_t a3 = f2tf(ap[4 * SX4 + 8]);
            const uint32_t* bp  = Wt + (s * 32 + cl + tg) * 24 + g;
            const uint32_t* bp2 = bp + 4 * 24;
            #pragma unroll
            for (int nt = 0; nt < 3; nt++)
                mma_tf32(acc[nt], a0, a1, a2, a3, bp[nt * 8], bp2[nt * 8]);
        }
    }

    const int px = pb + px0 + g;
    #pragma unroll
    for (int nt = 0; nt < 3; nt++) {
        const int n = nt * 8 + 2 * tg;
        if (n < K_) {
            float* o = out + ((size_t)b * K_ + n) * HW_ + px;
            o[0] = acc[nt][0];
            o[8] = acc[nt][2];
        }
        if (n + 1 < K_) {
            float* o = out + ((size_t)b * K_ + n + 1) * HW_ + px;
            o[0] = acc[nt][1];
            o[8] = acc[nt][3];
        }
    }
}

// -------------------------------------------------------------------------
extern "C" void kernel_launch(void* const* d_in, const int* in_sizes, int n_in,
                              void* d_out, int out_size)
{
    const float* x  = (const float*)d_in[0];
    const float* Wm = (const float*)d_in[1];
    const float* bm = (const float*)d_in[2];
    const float* Wf = (const float*)d_in[3];
    const float* bf = (const float*)d_in[4];
    float* out = (float*)d_out;

    cudaFuncSetAttribute(k1_fused, cudaFuncAttributeMaxDynamicSharedMemorySize, K1_SMEM);
    cudaFuncSetAttribute(k4_mma,   cudaFuncAttributeMaxDynamicSharedMemorySize, K4_SMEM);

    k1_fused  <<<B_ * NCHUNK, 256, K1_SMEM>>>(x, Wm, bm);
    k2_reduce <<<B_ * K_, 512>>>();
    k3_filters<<<dim3(K_, 64), 256>>>(Wf, bf);
    k4_mma    <<<B_ * 128, 256, K4_SMEM>>>(x, out);
}